// round 1
// baseline (speedup 1.0000x reference)
#include <cuda_runtime.h>
#include <cuda_bf16.h>
#include <math.h>

// Problem constants
#define BB 32
#define CC 256
#define HH 64
#define WW 64
#define OO 256
#define HID 65
#define KK 4

// Scratch (device globals: allocation-free per harness rules)
__device__ float g_pooled[BB * CC];                       // [B, C]
__device__ float g_attn[BB * KK * OO];                    // [B, K, O]
__device__ float g_aggw[(size_t)BB * OO * CC * 9];        // [B, O, C, 3, 3]  75.5 MB

// ---------------------------------------------------------------------------
// Kernel 1: global average pool.  grid = B*C blocks, 256 threads.
// x[b,c,:,:] is 4096 contiguous floats.
// ---------------------------------------------------------------------------
__global__ void pool_kernel(const float* __restrict__ x, float* __restrict__ pooled) {
    int bc = blockIdx.x;  // 0 .. B*C-1
    const float4* p = (const float4*)(x + (size_t)bc * (HH * WW));
    float s = 0.f;
    for (int i = threadIdx.x; i < (HH * WW) / 4; i += 256) {
        float4 v = p[i];
        s += (v.x + v.y) + (v.z + v.w);
    }
    // warp reduce
    for (int off = 16; off > 0; off >>= 1) s += __shfl_down_sync(0xffffffffu, s, off);
    __shared__ float red[8];
    int lane = threadIdx.x & 31, warp = threadIdx.x >> 5;
    if (lane == 0) red[warp] = s;
    __syncthreads();
    if (threadIdx.x == 0) {
        float t = 0.f;
        #pragma unroll
        for (int i = 0; i < 8; ++i) t += red[i];
        pooled[bc] = t * (1.0f / (HH * WW));
    }
}

// ---------------------------------------------------------------------------
// Kernel 2: MLP + softmax over K.  grid = B blocks, 256 threads.
//   h   = relu(pooled @ w1^T)          [HID]
//   lg  = (h @ w2^T + b2) / TEMP       [K, O]   (TEMP = 0.5 -> *2)
//   attn = softmax over K
// ---------------------------------------------------------------------------
__global__ void mlp_kernel(const float* __restrict__ pooled,
                           const float* __restrict__ w1,
                           const float* __restrict__ w2,
                           const float* __restrict__ b2,
                           float* __restrict__ attn) {
    int b = blockIdx.x;
    int tid = threadIdx.x;
    __shared__ float ps[CC];
    __shared__ float hs[HID];
    ps[tid] = pooled[b * CC + tid];
    __syncthreads();
    if (tid < HID) {
        float s = 0.f;
        const float* w1r = w1 + tid * CC;
        for (int c = 0; c < CC; ++c) s += ps[c] * w1r[c];
        hs[tid] = fmaxf(s, 0.f);
    }
    __syncthreads();
    int o = tid;  // 0..255
    float lg[KK];
    #pragma unroll
    for (int k = 0; k < KK; ++k) {
        int m = k * OO + o;
        float s = b2[m];
        const float* w2r = w2 + m * HID;
        for (int j = 0; j < HID; ++j) s += hs[j] * w2r[j];
        lg[k] = s * 2.0f;  // / TEMP
    }
    float mx = lg[0];
    #pragma unroll
    for (int k = 1; k < KK; ++k) mx = fmaxf(mx, lg[k]);
    float e[KK], sum = 0.f;
    #pragma unroll
    for (int k = 0; k < KK; ++k) { e[k] = __expf(lg[k] - mx); sum += e[k]; }
    float inv = 1.0f / sum;
    #pragma unroll
    for (int k = 0; k < KK; ++k) attn[(b * KK + k) * OO + o] = e[k] * inv;
}

// ---------------------------------------------------------------------------
// Kernel 3: agg_w[b,o,c,ij] = sum_k attn[b,k,o] * weight[k,o,c,ij]
// grid = B*O blocks, 256 threads.  Rows of 2304 are contiguous everywhere.
// ---------------------------------------------------------------------------
__global__ void aggw_kernel(const float* __restrict__ attn,
                            const float* __restrict__ weight,
                            float* __restrict__ aggw) {
    int bo = blockIdx.x;          // b*256 + o
    int b = bo >> 8;
    int o = bo & 255;
    float a0 = attn[(b * KK + 0) * OO + o];
    float a1 = attn[(b * KK + 1) * OO + o];
    float a2 = attn[(b * KK + 2) * OO + o];
    float a3 = attn[(b * KK + 3) * OO + o];
    const float* w0 = weight + (size_t)(0 * OO + o) * (CC * 9);
    const float* w1p = weight + (size_t)(1 * OO + o) * (CC * 9);
    const float* w2p = weight + (size_t)(2 * OO + o) * (CC * 9);
    const float* w3p = weight + (size_t)(3 * OO + o) * (CC * 9);
    float* dst = g_aggw + (size_t)bo * (CC * 9);
    for (int i = threadIdx.x; i < CC * 9; i += 256)
        dst[i] = a0 * w0[i] + a1 * w1p[i] + a2 * w2p[i] + a3 * w3p[i];
    (void)aggw;
}

// ---------------------------------------------------------------------------
// Kernel 4: per-sample 3x3 conv as implicit GEMM.
// Block tile: 64 output channels x (4 rows x 64 cols) pixels.
// Grid: 2048 blocks  (16 h-tiles) x (4 o-tiles) x (32 batches), 256 threads.
// Thread tile: 8 o x 8 pixels (1 row x 8 consecutive cols).
// Warp = one group of 8 o's (w-tile smem reads are uniform -> broadcast).
// ---------------------------------------------------------------------------
__global__ void __launch_bounds__(256, 2)
conv_kernel(const float* __restrict__ x, float* __restrict__ out) {
    int blk = blockIdx.x;
    int ht = blk & 15;          // h-tile: rows ht*4 .. +3
    int ot = (blk >> 4) & 3;    // o-tile: 64 o's
    int b  = blk >> 6;

    int tid  = threadIdx.x;
    int warp = tid >> 5;        // 0..7 -> o group (8 o's each)
    int lane = tid & 31;
    int prow = lane >> 3;       // 0..3 -> pixel row within tile
    int pcg  = lane & 7;        // 0..7 -> col group (8 cols each)

    int h0 = ht * 4;

    __shared__ float xs[8][6][66];   // [c][row -1..+4][col -1..64]
    __shared__ float ws[64][72];     // [o_local][c_local*9 + r*3 + s]

    float acc[8][8];
    #pragma unroll
    for (int i = 0; i < 8; ++i)
        #pragma unroll
        for (int j = 0; j < 8; ++j) acc[i][j] = 0.f;

    const float* xb = x + (size_t)b * CC * HH * WW;
    const float* wb = g_aggw + (size_t)(b * OO + ot * 64) * (CC * 9);

    for (int c0 = 0; c0 < CC; c0 += 8) {
        __syncthreads();
        // --- load w tile: 64 o x 72 (c,rs) = 4608 floats, contiguous per o row
        {
            const float* src = wb + c0 * 9;
            #pragma unroll
            for (int it = 0; it < 18; ++it) {
                int i = tid + it * 256;          // 0..4607
                int ol = i / 72;
                int t  = i - ol * 72;
                ws[ol][t] = src[(size_t)ol * (CC * 9) + t];
            }
        }
        // --- load x halo tile: 8 c x 6 rows x 66 cols = 3168 floats
        for (int i = tid; i < 8 * 6 * 66; i += 256) {
            int c   = i / 396;
            int rem = i - c * 396;
            int rr  = rem / 66;
            int cc  = rem - rr * 66;
            int h   = h0 + rr - 1;
            int gc  = cc - 1;
            float v = 0.f;
            if ((unsigned)h < (unsigned)HH && (unsigned)gc < (unsigned)WW)
                v = xb[((size_t)(c0 + c) * HH + h) * WW + gc];
            xs[c][rr][cc] = v;
        }
        __syncthreads();

        #pragma unroll
        for (int c = 0; c < 8; ++c) {
            #pragma unroll
            for (int r = 0; r < 3; ++r) {
                float xv[10];
                #pragma unroll
                for (int i = 0; i < 10; ++i)
                    xv[i] = xs[c][prow + r][pcg * 8 + i];
                #pragma unroll
                for (int s = 0; s < 3; ++s) {
                    int t = c * 9 + r * 3 + s;
                    #pragma unroll
                    for (int io = 0; io < 8; ++io) {
                        float wv = ws[warp * 8 + io][t];
                        #pragma unroll
                        for (int jj = 0; jj < 8; ++jj)
                            acc[io][jj] = fmaf(wv, xv[jj + s], acc[io][jj]);
                    }
                }
            }
        }
    }

    // epilogue: two float4 stores per o
    #pragma unroll
    for (int io = 0; io < 8; ++io) {
        int o = ot * 64 + warp * 8 + io;
        float* op = out + ((size_t)(b * OO + o) * HH + (h0 + prow)) * WW + pcg * 8;
        float4 v0 = make_float4(acc[io][0], acc[io][1], acc[io][2], acc[io][3]);
        float4 v1 = make_float4(acc[io][4], acc[io][5], acc[io][6], acc[io][7]);
        ((float4*)op)[0] = v0;
        ((float4*)op)[1] = v1;
    }
}

// ---------------------------------------------------------------------------
extern "C" void kernel_launch(void* const* d_in, const int* in_sizes, int n_in,
                              void* d_out, int out_size) {
    const float* x      = (const float*)d_in[0];  // [32,256,64,64]
    const float* w1     = (const float*)d_in[1];  // [65,256]
    const float* w2     = (const float*)d_in[2];  // [1024,65]
    const float* b2     = (const float*)d_in[3];  // [1024]
    const float* weight = (const float*)d_in[4];  // [4,256,256,3,3]
    float* out = (float*)d_out;                   // [32,256,64,64]

    float* pooled; cudaGetSymbolAddress((void**)&pooled, g_pooled);
    float* attn;   cudaGetSymbolAddress((void**)&attn,   g_attn);
    float* aggw;   cudaGetSymbolAddress((void**)&aggw,   g_aggw);

    pool_kernel<<<BB * CC, 256>>>(x, pooled);
    mlp_kernel<<<BB, 256>>>(pooled, w1, w2, b2, attn);
    aggw_kernel<<<BB * OO, 256>>>(attn, weight, aggw);
    conv_kernel<<<BB * 4 * 16, 256>>>(x, out);

    (void)in_sizes; (void)n_in; (void)out_size;
}